// round 1
// baseline (speedup 1.0000x reference)
#include <cuda_runtime.h>
#include <math.h>

// Problem constants
#define NB 2
#define SQ 2048
#define NTOK 4096      // NB*SQ
#define DM 512
#define NH 8
#define DK 64
#define NL 6
#define DFF 2048
#define NV 1024

// ---------------- scratch (no cudaMalloc allowed) ----------------
__device__ float g_x [NTOK * DM];
__device__ float g_h [NTOK * DM];
__device__ float g_q [NTOK * DM];
__device__ float g_k [NTOK * DM];
__device__ float g_v [NTOK * DM];
__device__ float g_ff[NTOK * DFF];

// ---------------- embedding + sinusoidal positional encoding ----------------
__global__ __launch_bounds__(256) void embed_kernel(const int* __restrict__ ids,
                                                    const float* __restrict__ emb,
                                                    float* __restrict__ x) {
    int idx = blockIdx.x * 256 + threadIdx.x;
    if (idx >= NTOK * DM) return;
    int row = idx >> 9;          // token row (D=512)
    int d   = idx & 511;
    int s   = row & (SQ - 1);
    int tok = ids[row];
    int i2  = d & ~1;
    // div = exp(-(2i) * ln(10000)/512)
    float div = expf(-(float)i2 * (9.210340371976184f / 512.0f));
    float ang = (float)s * div;
    float pe  = (d & 1) ? cosf(ang) : sinf(ang);
    x[idx] = emb[(size_t)tok * DM + d] + pe;
}

// ---------------- layernorm: one block per row of 512 ----------------
__global__ __launch_bounds__(256) void ln_kernel(const float* __restrict__ x,
                                                 const float* __restrict__ w,
                                                 const float* __restrict__ bias,
                                                 float* __restrict__ y) {
    __shared__ float sred[16];
    int row = blockIdx.x;
    int t = threadIdx.x;
    const float* xr = x + (size_t)row * DM;
    float v0 = xr[t];
    float v1 = xr[t + 256];
    float s = v0 + v1;
    #pragma unroll
    for (int off = 16; off; off >>= 1) s += __shfl_xor_sync(0xffffffffu, s, off);
    if ((t & 31) == 0) sred[t >> 5] = s;
    __syncthreads();
    float tot = 0.f;
    #pragma unroll
    for (int i = 0; i < 8; i++) tot += sred[i];
    float mu = tot * (1.0f / DM);
    float d0 = v0 - mu, d1 = v1 - mu;
    float s2 = d0 * d0 + d1 * d1;
    #pragma unroll
    for (int off = 16; off; off >>= 1) s2 += __shfl_xor_sync(0xffffffffu, s2, off);
    if ((t & 31) == 0) sred[8 + (t >> 5)] = s2;
    __syncthreads();
    float tot2 = 0.f;
    #pragma unroll
    for (int i = 0; i < 8; i++) tot2 += sred[8 + i];
    float var = tot2 * (1.0f / DM);
    float rstd = rsqrtf(var + 1e-5f);
    float* yr = y + (size_t)row * DM;
    yr[t]       = d0 * rstd * w[t]       + bias[t];
    yr[t + 256] = d1 * rstd * w[t + 256] + bias[t + 256];
}

// ---------------- SGEMM: C[N,M] = A[N,K] @ W[K,M] + bias (+relu) (+residual) ----------------
// Tiles: 128x128x8, 256 threads, 8x8 microtile per thread. All dims divide evenly.
__global__ __launch_bounds__(256) void sgemm_kernel(const float* __restrict__ A,
                                                    const float* __restrict__ W,
                                                    const float* __restrict__ bias,
                                                    const float* __restrict__ R,
                                                    float* __restrict__ C,
                                                    int N, int M, int K, int relu) {
    __shared__ float As[8][128];   // transposed A tile: As[k][m]
    __shared__ float Ws[8][128];   // natural W tile:    Ws[k][n]
    int tid = threadIdx.x;
    int row0 = blockIdx.y * 128;
    int col0 = blockIdx.x * 128;
    int ar = tid >> 1, ak = (tid & 1) * 4;       // A: 128 rows x 8 k
    int wr = tid >> 5, wc = (tid & 31) * 4;      // W: 8 k x 128 cols
    int mr = (tid >> 4) * 8;
    int nc = (tid & 15) * 8;
    float acc[8][8];
    #pragma unroll
    for (int i = 0; i < 8; i++)
        #pragma unroll
        for (int j = 0; j < 8; j++) acc[i][j] = 0.f;

    for (int k0 = 0; k0 < K; k0 += 8) {
        float4 av = *(const float4*)(A + (size_t)(row0 + ar) * K + k0 + ak);
        float4 wv = *(const float4*)(W + (size_t)(k0 + wr) * M + col0 + wc);
        __syncthreads();
        As[ak + 0][ar] = av.x;
        As[ak + 1][ar] = av.y;
        As[ak + 2][ar] = av.z;
        As[ak + 3][ar] = av.w;
        *(float4*)&Ws[wr][wc] = wv;
        __syncthreads();
        #pragma unroll
        for (int kk = 0; kk < 8; kk++) {
            float a[8], b[8];
            *(float4*)(a)     = *(const float4*)&As[kk][mr];
            *(float4*)(a + 4) = *(const float4*)&As[kk][mr + 4];
            *(float4*)(b)     = *(const float4*)&Ws[kk][nc];
            *(float4*)(b + 4) = *(const float4*)&Ws[kk][nc + 4];
            #pragma unroll
            for (int i = 0; i < 8; i++)
                #pragma unroll
                for (int j = 0; j < 8; j++)
                    acc[i][j] += a[i] * b[j];
        }
    }

    float bvals[8];
    *(float4*)(bvals)     = *(const float4*)(bias + col0 + nc);
    *(float4*)(bvals + 4) = *(const float4*)(bias + col0 + nc + 4);
    #pragma unroll
    for (int i = 0; i < 8; i++) {
        size_t off = (size_t)(row0 + mr + i) * M + col0 + nc;
        float out[8];
        #pragma unroll
        for (int j = 0; j < 8; j++) {
            float val = acc[i][j] + bvals[j];
            out[j] = val;
        }
        if (R) {
            float rv[8];
            *(float4*)(rv)     = *(const float4*)(R + off);
            *(float4*)(rv + 4) = *(const float4*)(R + off + 4);
            #pragma unroll
            for (int j = 0; j < 8; j++) out[j] += rv[j];
        }
        if (relu) {
            #pragma unroll
            for (int j = 0; j < 8; j++) out[j] = fmaxf(out[j], 0.f);
        }
        *(float4*)(C + off)     = *(float4*)(out);
        *(float4*)(C + off + 4) = *(float4*)(out + 4);
    }
}

// ---------------- Flash attention: 64-row Q tiles, causal, DK=64 ----------------
// grid = (32 q-tiles, B*H=16), 256 threads. Online softmax stats in registers
// (replicated across the 16 lanes that co-own each row group).
__global__ __launch_bounds__(256) void attn_kernel(const float* __restrict__ q,
                                                   const float* __restrict__ k,
                                                   const float* __restrict__ v,
                                                   float* __restrict__ out) {
    __shared__ float Qst[64 * 64];   // Qst[d][r]  (transposed)
    __shared__ float KVs[64 * 64];   // Kst[d][c] for K phase, Vs[kpos][d] for V phase
    __shared__ float Ps [64 * 64];   // P tile [r][c]
    int qt = blockIdx.x;
    int bh = blockIdx.y;
    int bb = bh >> 3;
    int hh = bh & 7;
    int tid = threadIdx.x;
    int tx = tid & 15, ty = tid >> 4;
    int r0 = ty * 4, c0 = tx * 4;
    const size_t base = (size_t)bb * SQ * DM + (size_t)hh * DK;
    const float scale = 0.125f;   // 1/sqrt(64)

    // load Q tile transposed
    const float* qb = q + base + (size_t)(qt * 64) * DM;
    for (int f = tid; f < 1024; f += 256) {
        int r = f >> 4;
        int dg = (f & 15) << 2;
        float4 t4 = *(const float4*)(qb + (size_t)r * DM + dg);
        Qst[(dg + 0) * 64 + r] = t4.x;
        Qst[(dg + 1) * 64 + r] = t4.y;
        Qst[(dg + 2) * 64 + r] = t4.z;
        Qst[(dg + 3) * 64 + r] = t4.w;
    }

    float m[4]  = {-1e30f, -1e30f, -1e30f, -1e30f};
    float ls[4] = {0.f, 0.f, 0.f, 0.f};
    float o[16];
    #pragma unroll
    for (int i = 0; i < 16; i++) o[i] = 0.f;

    for (int kt = 0; kt <= qt; kt++) {
        // --- load K tile (transposed) ---
        const float* kb = k + base + (size_t)(kt * 64) * DM;
        __syncthreads();   // everyone done with V reads of previous iter (and Q load)
        for (int f = tid; f < 1024; f += 256) {
            int r = f >> 4;
            int dg = (f & 15) << 2;
            float4 t4 = *(const float4*)(kb + (size_t)r * DM + dg);
            KVs[(dg + 0) * 64 + r] = t4.x;
            KVs[(dg + 1) * 64 + r] = t4.y;
            KVs[(dg + 2) * 64 + r] = t4.z;
            KVs[(dg + 3) * 64 + r] = t4.w;
        }
        __syncthreads();

        // --- S = Q K^T (4x4 microtile) ---
        float s[16];
        #pragma unroll
        for (int i = 0; i < 16; i++) s[i] = 0.f;
        #pragma unroll 8
        for (int d = 0; d < 64; d++) {
            float4 a  = *(const float4*)&Qst[d * 64 + r0];
            float4 b4 = *(const float4*)&KVs[d * 64 + c0];
            s[ 0] += a.x * b4.x; s[ 1] += a.x * b4.y; s[ 2] += a.x * b4.z; s[ 3] += a.x * b4.w;
            s[ 4] += a.y * b4.x; s[ 5] += a.y * b4.y; s[ 6] += a.y * b4.z; s[ 7] += a.y * b4.w;
            s[ 8] += a.z * b4.x; s[ 9] += a.z * b4.y; s[10] += a.z * b4.z; s[11] += a.z * b4.w;
            s[12] += a.w * b4.x; s[13] += a.w * b4.y; s[14] += a.w * b4.z; s[15] += a.w * b4.w;
        }
        bool last = (kt == qt);
        #pragma unroll
        for (int i = 0; i < 4; i++)
            #pragma unroll
            for (int j = 0; j < 4; j++) {
                float val = s[i * 4 + j] * scale;
                if (last && (c0 + j > r0 + i)) val = -1e30f;
                s[i * 4 + j] = val;
            }

        // --- online softmax per row group (16 lanes share each row) ---
        #pragma unroll
        for (int i = 0; i < 4; i++) {
            float mt = fmaxf(fmaxf(s[i*4+0], s[i*4+1]), fmaxf(s[i*4+2], s[i*4+3]));
            #pragma unroll
            for (int off = 8; off; off >>= 1)
                mt = fmaxf(mt, __shfl_xor_sync(0xffffffffu, mt, off));
            float mnew = fmaxf(m[i], mt);
            float resc = __expf(m[i] - mnew);
            float psum = 0.f;
            #pragma unroll
            for (int j = 0; j < 4; j++) {
                float p = __expf(s[i * 4 + j] - mnew);
                s[i * 4 + j] = p;
                psum += p;
            }
            #pragma unroll
            for (int off = 8; off; off >>= 1)
                psum += __shfl_xor_sync(0xffffffffu, psum, off);
            ls[i] = ls[i] * resc + psum;
            m[i] = mnew;
            #pragma unroll
            for (int j = 0; j < 4; j++) o[i * 4 + j] *= resc;
            *(float4*)&Ps[(r0 + i) * 64 + c0] =
                make_float4(s[i*4+0], s[i*4+1], s[i*4+2], s[i*4+3]);
        }
        __syncthreads();   // P visible; K reads done -> safe to overwrite KVs

        // --- load V tile (natural layout) ---
        const float* vb = v + base + (size_t)(kt * 64) * DM;
        for (int f = tid; f < 1024; f += 256) {
            int r = f >> 4;
            int dg = (f & 15) << 2;
            *(float4*)&KVs[r * 64 + dg] = *(const float4*)(vb + (size_t)r * DM + dg);
        }
        __syncthreads();

        // --- O += P @ V ---
        #pragma unroll 8
        for (int kk = 0; kk < 64; kk++) {
            float4 b4 = *(const float4*)&KVs[kk * 64 + c0];
            float a0 = Ps[(r0 + 0) * 64 + kk];
            float a1 = Ps[(r0 + 1) * 64 + kk];
            float a2 = Ps[(r0 + 2) * 64 + kk];
            float a3 = Ps[(r0 + 3) * 64 + kk];
            o[ 0] += a0 * b4.x; o[ 1] += a0 * b4.y; o[ 2] += a0 * b4.z; o[ 3] += a0 * b4.w;
            o[ 4] += a1 * b4.x; o[ 5] += a1 * b4.y; o[ 6] += a1 * b4.z; o[ 7] += a1 * b4.w;
            o[ 8] += a2 * b4.x; o[ 9] += a2 * b4.y; o[10] += a2 * b4.z; o[11] += a2 * b4.w;
            o[12] += a3 * b4.x; o[13] += a3 * b4.y; o[14] += a3 * b4.z; o[15] += a3 * b4.w;
        }
    }

    // write O / l
    float* ob = out + base + (size_t)(qt * 64) * DM;
    #pragma unroll
    for (int i = 0; i < 4; i++) {
        float inv = 1.0f / ls[i];
        *(float4*)(ob + (size_t)(r0 + i) * DM + c0) =
            make_float4(o[i*4+0]*inv, o[i*4+1]*inv, o[i*4+2]*inv, o[i*4+3]*inv);
    }
}

// ---------------- host ----------------
static void run_gemm(const float* A, const float* W, const float* bias, const float* R,
                     float* C, int N, int M, int K, int relu) {
    dim3 grid(M / 128, N / 128);
    sgemm_kernel<<<grid, 256>>>(A, W, bias, R, C, N, M, K, relu);
}

extern "C" void kernel_launch(void* const* d_in, const int* in_sizes, int n_in,
                              void* d_out, int out_size) {
    (void)in_sizes; (void)n_in; (void)out_size;
    const int*   ids  = (const int*)  d_in[0];
    const float* emb  = (const float*)d_in[1];
    const float* wq   = (const float*)d_in[2];
    const float* bq   = (const float*)d_in[3];
    const float* wk   = (const float*)d_in[4];
    const float* bk   = (const float*)d_in[5];
    const float* wv   = (const float*)d_in[6];
    const float* bv   = (const float*)d_in[7];
    const float* wo   = (const float*)d_in[8];
    const float* bo   = (const float*)d_in[9];
    const float* ln1w = (const float*)d_in[10];
    const float* ln1b = (const float*)d_in[11];
    const float* ln2w = (const float*)d_in[12];
    const float* ln2b = (const float*)d_in[13];
    const float* w1   = (const float*)d_in[14];
    const float* b1   = (const float*)d_in[15];
    const float* w2   = (const float*)d_in[16];
    const float* b2   = (const float*)d_in[17];
    const float* outw = (const float*)d_in[18];
    const float* outb = (const float*)d_in[19];

    float *x, *h, *q, *k, *v, *ff;
    cudaGetSymbolAddress((void**)&x,  g_x);
    cudaGetSymbolAddress((void**)&h,  g_h);
    cudaGetSymbolAddress((void**)&q,  g_q);
    cudaGetSymbolAddress((void**)&k,  g_k);
    cudaGetSymbolAddress((void**)&v,  g_v);
    cudaGetSymbolAddress((void**)&ff, g_ff);

    embed_kernel<<<(NTOK * DM) / 256, 256>>>(ids, emb, x);

    for (int l = 0; l < NL; l++) {
        size_t offDD  = (size_t)l * DM * DM;
        size_t offD   = (size_t)l * DM;
        size_t offDF  = (size_t)l * DM * DFF;
        size_t offF   = (size_t)l * DFF;

        ln_kernel<<<NTOK, 256>>>(x, ln1w + offD, ln1b + offD, h);
        run_gemm(h, wq + offDD, bq + offD, nullptr, q, NTOK, DM, DM, 0);
        run_gemm(h, wk + offDD, bk + offD, nullptr, k, NTOK, DM, DM, 0);
        run_gemm(h, wv + offDD, bv + offD, nullptr, v, NTOK, DM, DM, 0);
        attn_kernel<<<dim3(SQ / 64, NB * NH), 256>>>(q, k, v, h);
        run_gemm(h, wo + offDD, bo + offD, nullptr, x, NTOK, DM, DM, 0);   // no residual (faithful)
        ln_kernel<<<NTOK, 256>>>(x, ln2w + offD, ln2b + offD, q);          // h2 in q buffer
        run_gemm(q, w1 + offDF, b1 + offF, nullptr, ff, NTOK, DFF, DM, 1); // relu
        run_gemm(ff, w2 + offDF, b2 + offD, x /*residual*/, x, NTOK, DM, DFF, 0);
    }

    run_gemm(x, outw, outb, nullptr, (float*)d_out, NTOK, NV, DM, 0);
}

// round 3
// speedup vs baseline: 3.0533x; 3.0533x over previous
#include <cuda_runtime.h>
#include <math.h>
#include <stdint.h>

// ---------------- problem constants ----------------
#define NB 2
#define SQ 2048
#define NTOK 4096      // NB*SQ
#define DM 512
#define NH 8
#define DK 64
#define NL 6
#define DFF 2048
#define NV 1024
#define QKVW 1536      // packed q|k|v width

// ---------------- scratch (no cudaMalloc allowed) ----------------
__device__ float g_x   [NTOK * DM];
__device__ float g_h   [NTOK * DM];
__device__ float g_qkv [NTOK * QKVW];
__device__ float g_ff  [NTOK * DFF];
// K-major (transposed) weights
__device__ float g_wqkvT[NL * QKVW * DM];
__device__ float g_woT  [NL * DM * DM];
__device__ float g_w1T  [NL * DFF * DM];
__device__ float g_w2T  [NL * DM * DFF];
__device__ float g_outwT[NV * DM];
__device__ float g_bqkv [NL * QKVW];

// ---------------- tf32 helpers ----------------
__device__ __forceinline__ uint32_t f2tf(float f) {
    uint32_t r;
    asm("cvt.rna.tf32.f32 %0, %1;" : "=r"(r) : "f"(f));
    return r;
}

__device__ __forceinline__ void mma8(float* c, const uint32_t* a, const uint32_t* b) {
    asm volatile(
        "mma.sync.aligned.m16n8k8.row.col.f32.tf32.tf32.f32 "
        "{%0,%1,%2,%3}, {%4,%5,%6,%7}, {%8,%9}, {%0,%1,%2,%3};\n"
        : "+f"(c[0]), "+f"(c[1]), "+f"(c[2]), "+f"(c[3])
        : "r"(a[0]), "r"(a[1]), "r"(a[2]), "r"(a[3]), "r"(b[0]), "r"(b[1]));
}

// ---------------- tf32 mma GEMM: C[4096,M] = A[4096,K] @ Wt[M,K]^T + bias ----------------
// CTA 128x128, k-tile 32, 256 threads, warp tile 64x32. Double-buffered SMEM (pitch 36).
#define GP 36
#define GSTAGE 9216            // uints per stage (A 4608 + B 4608)
#define GEMM_SMEM (2 * GSTAGE * 4)

__global__ __launch_bounds__(256) void mma_gemm(const float* __restrict__ A,
                                                const float* __restrict__ Wt,
                                                const float* __restrict__ bias,
                                                const float* __restrict__ R,
                                                float* __restrict__ C,
                                                int K, int M, int relu) {
    extern __shared__ uint32_t sm[];
    int t = threadIdx.x, lane = t & 31, wid = t >> 5;
    int wm = wid & 1, wn = wid >> 1;
    int gr = lane >> 2, lc = lane & 3;
    int row0 = blockIdx.y * 128, col0 = blockIdx.x * 128;
    const int NC = K >> 5;

    float acc[4][4][4];
    #pragma unroll
    for (int i = 0; i < 4; i++)
        #pragma unroll
        for (int j = 0; j < 4; j++)
            #pragma unroll
            for (int k = 0; k < 4; k++) acc[i][j][k] = 0.f;

    float4 ra[4], rb[4];
    // prologue: load chunk 0
    #pragma unroll
    for (int i = 0; i < 4; i++) {
        int idx = i * 256 + t, r = idx >> 3, c = (idx & 7) << 2;
        ra[i] = *(const float4*)(A  + (size_t)(row0 + r) * K + c);
        rb[i] = *(const float4*)(Wt + (size_t)(col0 + r) * K + c);
    }
    {
        uint32_t* Ab = sm;
        uint32_t* Bb = sm + 4608;
        #pragma unroll
        for (int i = 0; i < 4; i++) {
            int idx = i * 256 + t, r = idx >> 3, c = (idx & 7) << 2, off = r * GP + c;
            *(uint4*)(Ab + off) = make_uint4(f2tf(ra[i].x), f2tf(ra[i].y), f2tf(ra[i].z), f2tf(ra[i].w));
            *(uint4*)(Bb + off) = make_uint4(f2tf(rb[i].x), f2tf(rb[i].y), f2tf(rb[i].z), f2tf(rb[i].w));
        }
    }
    __syncthreads();

    for (int cch = 0; cch < NC; cch++) {
        if (cch + 1 < NC) {
            int k0 = (cch + 1) << 5;
            #pragma unroll
            for (int i = 0; i < 4; i++) {
                int idx = i * 256 + t, r = idx >> 3, c = (idx & 7) << 2;
                ra[i] = *(const float4*)(A  + (size_t)(row0 + r) * K + k0 + c);
                rb[i] = *(const float4*)(Wt + (size_t)(col0 + r) * K + k0 + c);
            }
        }
        {
            const uint32_t* Ab = sm + (cch & 1) * GSTAGE;
            const uint32_t* Bb = Ab + 4608;
            const uint32_t* Abase = Ab + (wm * 64 + gr) * GP + lc;
            const uint32_t* Bbase = Bb + (wn * 32 + gr) * GP + lc;
            #pragma unroll
            for (int ks = 0; ks < 4; ks++) {
                uint32_t a[4][4], b[4][2];
                #pragma unroll
                for (int mt = 0; mt < 4; mt++) {
                    const uint32_t* p = Abase + mt * 16 * GP + ks * 8;
                    a[mt][0] = p[0]; a[mt][1] = p[8 * GP]; a[mt][2] = p[4]; a[mt][3] = p[8 * GP + 4];
                }
                #pragma unroll
                for (int nt = 0; nt < 4; nt++) {
                    const uint32_t* p = Bbase + nt * 8 * GP + ks * 8;
                    b[nt][0] = p[0]; b[nt][1] = p[4];
                }
                #pragma unroll
                for (int mt = 0; mt < 4; mt++)
                    #pragma unroll
                    for (int nt = 0; nt < 4; nt++)
                        mma8(acc[mt][nt], a[mt], b[nt]);
            }
        }
        if (cch + 1 < NC) {
            __syncthreads();
            uint32_t* Ab = sm + ((cch + 1) & 1) * GSTAGE;
            uint32_t* Bb = Ab + 4608;
            #pragma unroll
            for (int i = 0; i < 4; i++) {
                int idx = i * 256 + t, r = idx >> 3, c = (idx & 7) << 2, off = r * GP + c;
                *(uint4*)(Ab + off) = make_uint4(f2tf(ra[i].x), f2tf(ra[i].y), f2tf(ra[i].z), f2tf(ra[i].w));
                *(uint4*)(Bb + off) = make_uint4(f2tf(rb[i].x), f2tf(rb[i].y), f2tf(rb[i].z), f2tf(rb[i].w));
            }
            __syncthreads();
        }
    }

    // epilogue
    #pragma unroll
    for (int mt = 0; mt < 4; mt++) {
        int r = row0 + wm * 64 + mt * 16 + gr;
        #pragma unroll
        for (int nt = 0; nt < 4; nt++) {
            int c = col0 + wn * 32 + nt * 8 + lc * 2;
            float b0 = bias[c], b1 = bias[c + 1];
            #pragma unroll
            for (int h2 = 0; h2 < 2; h2++) {
                size_t off = (size_t)(r + h2 * 8) * M + c;
                float v0 = acc[mt][nt][h2 * 2 + 0] + b0;
                float v1 = acc[mt][nt][h2 * 2 + 1] + b1;
                if (R) {
                    float2 rv = *(const float2*)(R + off);
                    v0 += rv.x; v1 += rv.y;
                }
                if (relu) { v0 = fmaxf(v0, 0.f); v1 = fmaxf(v1, 0.f); }
                *(float2*)(C + off) = make_float2(v0, v1);
            }
        }
    }
}

// ---------------- flash attention with tf32 mma ----------------
// 128 threads (4 warps), 64 q-rows per CTA, per (b,h). Warp w owns rows [w*16, w*16+16).
#define AP 68
#define ATTN_SMEM ((3 * 64 * AP + 192) * 4)

__global__ __launch_bounds__(128) void attn_mma(const float* __restrict__ qkv,
                                                float* __restrict__ out) {
    extern __shared__ uint32_t smu[];
    uint32_t* Qs = smu;
    uint32_t* Ks = smu + 64 * AP;
    float*    Ps = (float*)(smu + 2 * 64 * AP);
    float*  sm_m = (float*)(smu + 3 * 64 * AP);
    float*  sm_l = sm_m + 64;
    float* sm_rs = sm_m + 128;

    int qt = blockIdx.x, bh = blockIdx.y, bb = bh >> 3, hh = bh & 7;
    int t = threadIdx.x, lane = t & 31, wid = t >> 5;
    int gr = lane >> 2, lc = lane & 3;
    int mrow = wid * 16 + gr;
    const size_t base = (size_t)bb * SQ * QKVW + hh * DK;

    // Q tile
    const float* qb = qkv + base + (size_t)qt * 64 * QKVW;
    #pragma unroll
    for (int i = 0; i < 8; i++) {
        int f = i * 128 + t, r = f >> 4, d4 = (f & 15) << 2;
        float4 v = *(const float4*)(qb + (size_t)r * QKVW + d4);
        *(uint4*)(Qs + r * AP + d4) = make_uint4(f2tf(v.x), f2tf(v.y), f2tf(v.z), f2tf(v.w));
    }
    if (t < 64) { sm_m[t] = -1e30f; sm_l[t] = 0.f; }

    float co[8][4];
    #pragma unroll
    for (int i = 0; i < 8; i++)
        #pragma unroll
        for (int j = 0; j < 4; j++) co[i][j] = 0.f;

    for (int kt = 0; kt <= qt; kt++) {
        __syncthreads();   // prev PV done with Ps/Ks; Q visible (first iter)
        const float* kb = qkv + base + 512 + (size_t)kt * 64 * QKVW;
        #pragma unroll
        for (int i = 0; i < 8; i++) {
            int f = i * 128 + t, r = f >> 4, d4 = (f & 15) << 2;
            float4 v = *(const float4*)(kb + (size_t)r * QKVW + d4);
            *(uint4*)(Ks + r * AP + d4) = make_uint4(f2tf(v.x), f2tf(v.y), f2tf(v.z), f2tf(v.w));
        }
        __syncthreads();

        // S = Q @ K^T
        float cs[8][4];
        #pragma unroll
        for (int i = 0; i < 8; i++)
            #pragma unroll
            for (int j = 0; j < 4; j++) cs[i][j] = 0.f;
        {
            const uint32_t* Abase = Qs + mrow * AP + lc;
            const uint32_t* Bbase = Ks + gr * AP + lc;
            #pragma unroll
            for (int ks = 0; ks < 8; ks++) {
                uint32_t a[4];
                const uint32_t* p = Abase + ks * 8;
                a[0] = p[0]; a[1] = p[8 * AP]; a[2] = p[4]; a[3] = p[8 * AP + 4];
                #pragma unroll
                for (int nt = 0; nt < 8; nt++) {
                    const uint32_t* q2 = Bbase + nt * 8 * AP + ks * 8;
                    uint32_t b[2] = {q2[0], q2[4]};
                    mma8(cs[nt], a, b);
                }
            }
        }
        #pragma unroll
        for (int nt = 0; nt < 8; nt++) {
            int c = nt * 8 + lc * 2;
            *(float2*)(Ps + mrow * AP + c)       = make_float2(cs[nt][0], cs[nt][1]);
            *(float2*)(Ps + (mrow + 8) * AP + c) = make_float2(cs[nt][2], cs[nt][3]);
        }
        __syncthreads();

        // online softmax: thread pair per row
        {
            int r = t >> 1, half = t & 1;
            int qrow = qt * 64 + r;
            int kbase0 = kt * 64 + half * 32;
            float* rowp = Ps + r * AP + half * 32;
            float vals[32];
            float mx = -1e30f;
            bool edge = (kt == qt);
            #pragma unroll
            for (int j = 0; j < 32; j += 4) {
                float4 v4 = *(const float4*)(rowp + j);
                float w0 = v4.x * 0.125f, w1 = v4.y * 0.125f;
                float w2 = v4.z * 0.125f, w3 = v4.w * 0.125f;
                if (edge) {
                    if (kbase0 + j + 0 > qrow) w0 = -1e30f;
                    if (kbase0 + j + 1 > qrow) w1 = -1e30f;
                    if (kbase0 + j + 2 > qrow) w2 = -1e30f;
                    if (kbase0 + j + 3 > qrow) w3 = -1e30f;
                }
                vals[j] = w0; vals[j+1] = w1; vals[j+2] = w2; vals[j+3] = w3;
                mx = fmaxf(mx, fmaxf(fmaxf(w0, w1), fmaxf(w2, w3)));
            }
            mx = fmaxf(mx, __shfl_xor_sync(0xffffffffu, mx, 1));
            float mo = sm_m[r];
            float mn = fmaxf(mo, mx);
            float rs = __expf(mo - mn);
            float ssum = 0.f;
            #pragma unroll
            for (int j = 0; j < 32; j += 4) {
                float p0 = __expf(vals[j]   - mn), p1 = __expf(vals[j+1] - mn);
                float p2 = __expf(vals[j+2] - mn), p3 = __expf(vals[j+3] - mn);
                ssum += (p0 + p1) + (p2 + p3);
                *(uint4*)(rowp + j) = make_uint4(f2tf(p0), f2tf(p1), f2tf(p2), f2tf(p3));
            }
            ssum += __shfl_xor_sync(0xffffffffu, ssum, 1);
            if (!half) { sm_l[r] = sm_l[r] * rs + ssum; sm_m[r] = mn; sm_rs[r] = rs; }
        }

        // V tile transposed (kk along lanes -> conflict-free STS)
        const float* vb = qkv + base + 1024 + (size_t)kt * 64 * QKVW;
        #pragma unroll
        for (int i = 0; i < 8; i++) {
            int kk = t & 63;
            int d4 = (i * 2 + (t >> 6)) * 4;
            float4 v = *(const float4*)(vb + (size_t)kk * QKVW + d4);
            Ks[(d4 + 0) * AP + kk] = f2tf(v.x);
            Ks[(d4 + 1) * AP + kk] = f2tf(v.y);
            Ks[(d4 + 2) * AP + kk] = f2tf(v.z);
            Ks[(d4 + 3) * AP + kk] = f2tf(v.w);
        }
        __syncthreads();

        // rescale O, then O += P @ V
        {
            float rs0 = sm_rs[mrow], rs1 = sm_rs[mrow + 8];
            #pragma unroll
            for (int nt = 0; nt < 8; nt++) {
                co[nt][0] *= rs0; co[nt][1] *= rs0;
                co[nt][2] *= rs1; co[nt][3] *= rs1;
            }
            const uint32_t* Pb = (const uint32_t*)Ps + mrow * AP + lc;
            const uint32_t* Bbase = Ks + gr * AP + lc;
            #pragma unroll
            for (int ks = 0; ks < 8; ks++) {
                uint32_t a[4];
                const uint32_t* p = Pb + ks * 8;
                a[0] = p[0]; a[1] = p[8 * AP]; a[2] = p[4]; a[3] = p[8 * AP + 4];
                #pragma unroll
                for (int nt = 0; nt < 8; nt++) {
                    const uint32_t* q2 = Bbase + nt * 8 * AP + ks * 8;
                    uint32_t b[2] = {q2[0], q2[4]};
                    mma8(co[nt], a, b);
                }
            }
        }
    }

    float inv0 = 1.f / sm_l[mrow], inv1 = 1.f / sm_l[mrow + 8];
    float* ob = out + ((size_t)bb * SQ + (size_t)qt * 64) * DM + hh * DK;
    #pragma unroll
    for (int nt = 0; nt < 8; nt++) {
        int c = nt * 8 + lc * 2;
        *(float2*)(ob + (size_t)mrow * DM + c) =
            make_float2(co[nt][0] * inv0, co[nt][1] * inv0);
        *(float2*)(ob + (size_t)(mrow + 8) * DM + c) =
            make_float2(co[nt][2] * inv1, co[nt][3] * inv1);
    }
}

// ---------------- weight transpose: in[R][C] -> out[C][R] ----------------
__global__ __launch_bounds__(256) void transpose_k(const float* __restrict__ in,
                                                   float* __restrict__ out,
                                                   int R, int C,
                                                   size_t in_z, size_t out_z) {
    __shared__ float tbuf[32][33];
    in  += blockIdx.z * in_z;
    out += blockIdx.z * out_z;
    int c0 = blockIdx.x * 32, r0 = blockIdx.y * 32;
    #pragma unroll
    for (int i = 0; i < 32; i += 8)
        tbuf[threadIdx.y + i][threadIdx.x] = in[(size_t)(r0 + threadIdx.y + i) * C + c0 + threadIdx.x];
    __syncthreads();
    #pragma unroll
    for (int i = 0; i < 32; i += 8)
        out[(size_t)(c0 + threadIdx.y + i) * R + r0 + threadIdx.x] = tbuf[threadIdx.x][threadIdx.y + i];
}

// ---------------- pack q/k/v biases ----------------
__global__ __launch_bounds__(256) void biaspack_kernel(const float* __restrict__ bq,
                                                       const float* __restrict__ bk,
                                                       const float* __restrict__ bv,
                                                       float* __restrict__ dst) {
    int idx = blockIdx.x * 256 + threadIdx.x;
    if (idx >= NL * QKVW) return;
    int l = idx / QKVW, j = idx % QKVW;
    float v;
    if (j < 512)       v = bq[l * 512 + j];
    else if (j < 1024) v = bk[l * 512 + j - 512];
    else               v = bv[l * 512 + j - 1024];
    dst[idx] = v;
}

// ---------------- embedding + positional encoding ----------------
__global__ __launch_bounds__(256) void embed_kernel(const int* __restrict__ ids,
                                                    const float* __restrict__ emb,
                                                    float* __restrict__ x) {
    int idx = blockIdx.x * 256 + threadIdx.x;
    if (idx >= NTOK * DM) return;
    int row = idx >> 9;
    int d   = idx & 511;
    int s   = row & (SQ - 1);
    int tok = ids[row];
    int i2  = d & ~1;
    float div = expf(-(float)i2 * (9.210340371976184f / 512.0f));
    float ang = (float)s * div;
    float pe  = (d & 1) ? cosf(ang) : sinf(ang);
    x[idx] = emb[(size_t)tok * DM + d] + pe;
}

// ---------------- layernorm ----------------
__global__ __launch_bounds__(256) void ln_kernel(const float* __restrict__ x,
                                                 const float* __restrict__ w,
                                                 const float* __restrict__ bias,
                                                 float* __restrict__ y) {
    __shared__ float sred[16];
    int row = blockIdx.x;
    int t = threadIdx.x;
    const float* xr = x + (size_t)row * DM;
    float v0 = xr[t];
    float v1 = xr[t + 256];
    float s = v0 + v1;
    #pragma unroll
    for (int off = 16; off; off >>= 1) s += __shfl_xor_sync(0xffffffffu, s, off);
    if ((t & 31) == 0) sred[t >> 5] = s;
    __syncthreads();
    float tot = 0.f;
    #pragma unroll
    for (int i = 0; i < 8; i++) tot += sred[i];
    float mu = tot * (1.0f / DM);
    float d0 = v0 - mu, d1 = v1 - mu;
    float s2 = d0 * d0 + d1 * d1;
    #pragma unroll
    for (int off = 16; off; off >>= 1) s2 += __shfl_xor_sync(0xffffffffu, s2, off);
    if ((t & 31) == 0) sred[8 + (t >> 5)] = s2;
    __syncthreads();
    float tot2 = 0.f;
    #pragma unroll
    for (int i = 0; i < 8; i++) tot2 += sred[8 + i];
    float var = tot2 * (1.0f / DM);
    float rstd = rsqrtf(var + 1e-5f);
    float* yr = y + (size_t)row * DM;
    yr[t]       = d0 * rstd * w[t]       + bias[t];
    yr[t + 256] = d1 * rstd * w[t + 256] + bias[t + 256];
}

// ---------------- host ----------------
static void run_gemm(const float* A, const float* Wt, const float* bias, const float* R,
                     float* C, int K, int M, int relu) {
    mma_gemm<<<dim3(M / 128, NTOK / 128), 256, GEMM_SMEM>>>(A, Wt, bias, R, C, K, M, relu);
}

extern "C" void kernel_launch(void* const* d_in, const int* in_sizes, int n_in,
                              void* d_out, int out_size) {
    (void)in_sizes; (void)n_in; (void)out_size;
    const int*   ids  = (const int*)  d_in[0];
    const float* emb  = (const float*)d_in[1];
    const float* wq   = (const float*)d_in[2];
    const float* bq   = (const float*)d_in[3];
    const float* wk   = (const float*)d_in[4];
    const float* bk   = (const float*)d_in[5];
    const float* wv   = (const float*)d_in[6];
    const float* bv   = (const float*)d_in[7];
    const float* wo   = (const float*)d_in[8];
    const float* bo   = (const float*)d_in[9];
    const float* ln1w = (const float*)d_in[10];
    const float* ln1b = (const float*)d_in[11];
    const float* ln2w = (const float*)d_in[12];
    const float* ln2b = (const float*)d_in[13];
    const float* w1   = (const float*)d_in[14];
    const float* b1   = (const float*)d_in[15];
    const float* w2   = (const float*)d_in[16];
    const float* b2   = (const float*)d_in[17];
    const float* outw = (const float*)d_in[18];
    const float* outb = (const float*)d_in[19];

    float *x, *h, *qkv, *ff, *wqkvT, *woT, *w1T, *w2T, *outwT, *bqkv;
    cudaGetSymbolAddress((void**)&x,     g_x);
    cudaGetSymbolAddress((void**)&h,     g_h);
    cudaGetSymbolAddress((void**)&qkv,   g_qkv);
    cudaGetSymbolAddress((void**)&ff,    g_ff);
    cudaGetSymbolAddress((void**)&wqkvT, g_wqkvT);
    cudaGetSymbolAddress((void**)&woT,   g_woT);
    cudaGetSymbolAddress((void**)&w1T,   g_w1T);
    cudaGetSymbolAddress((void**)&w2T,   g_w2T);
    cudaGetSymbolAddress((void**)&outwT, g_outwT);
    cudaGetSymbolAddress((void**)&bqkv,  g_bqkv);

    cudaFuncSetAttribute(mma_gemm, cudaFuncAttributeMaxDynamicSharedMemorySize, GEMM_SMEM);
    cudaFuncSetAttribute(attn_mma, cudaFuncAttributeMaxDynamicSharedMemorySize, ATTN_SMEM);

    dim3 tb(32, 8);
    transpose_k<<<dim3(16, 16, NL), tb>>>(wq, wqkvT + 0,       DM, DM, (size_t)DM*DM, (size_t)QKVW*DM);
    transpose_k<<<dim3(16, 16, NL), tb>>>(wk, wqkvT + DM*DM,   DM, DM, (size_t)DM*DM, (size_t)QKVW*DM);
    transpose_k<<<dim3(16, 16, NL), tb>>>(wv, wqkvT + 2*DM*DM, DM, DM, (size_t)DM*DM, (size_t)QKVW*DM);
    transpose_k<<<dim3(16, 16, NL), tb>>>(wo, woT,             DM, DM, (size_t)DM*DM, (size_t)DM*DM);
    transpose_k<<<dim3(DFF/32, 16, NL), tb>>>(w1, w1T, DM, DFF, (size_t)DM*DFF, (size_t)DM*DFF);
    transpose_k<<<dim3(16, DFF/32, NL), tb>>>(w2, w2T, DFF, DM, (size_t)DM*DFF, (size_t)DM*DFF);
    transpose_k<<<dim3(NV/32, 16, 1),   tb>>>(outw, outwT, DM, NV, 0, 0);
    biaspack_kernel<<<(NL * QKVW + 255) / 256, 256>>>(bq, bk, bv, bqkv);

    embed_kernel<<<(NTOK * DM) / 256, 256>>>(ids, emb, x);

    for (int l = 0; l < NL; l++) {
        size_t offD = (size_t)l * DM;
        size_t offF = (size_t)l * DFF;

        ln_kernel<<<NTOK, 256>>>(x, ln1w + offD, ln1b + offD, h);
        run_gemm(h, wqkvT + (size_t)l * QKVW * DM, bqkv + (size_t)l * QKVW, nullptr,
                 qkv, DM, QKVW, 0);
        attn_mma<<<dim3(SQ / 64, NB * NH), 128, ATTN_SMEM>>>(qkv, h);
        run_gemm(h, woT + (size_t)l * DM * DM, bo + offD, nullptr, x, DM, DM, 0);
        ln_kernel<<<NTOK, 256>>>(x, ln2w + offD, ln2b + offD, h);
        run_gemm(h, w1T + (size_t)l * DM * DFF, b1 + offF, nullptr, ff, DM, DFF, 1);
        run_gemm(ff, w2T + (size_t)l * DM * DFF, b2 + offD, x /*residual*/, x, DFF, DM, 0);
    }

    run_gemm(x, outwT, outb, nullptr, (float*)d_out, DM, NV, 0);
}